// round 2
// baseline (speedup 1.0000x reference)
#include <cuda_runtime.h>
#include <cstdint>
#include <math_constants.h>

#define NND 40000
#define HD  128
#define EED 640000

// ---------------- scratch (device globals: allocation-free) ----------------
__device__ float g_bufXW [(size_t)NND * HD];   // GEMM out (GCN xw) / GAT out
__device__ float g_bufACC[(size_t)NND * HD];   // GCN aggregate / relu output
__device__ float g_bufHH [(size_t)NND * HD];   // GAT transformed features
__device__ float g_bufOUT[(size_t)NND * HD];   // GAT result (next layer input)
__device__ int   g_deg  [NND];
__device__ float g_dinv [NND];
__device__ float g_alpha[EED];                 // per-edge alpha, then exp(alpha-amax)
__device__ float g_amax [NND];
__device__ float g_denom[NND];
__device__ float g_self [NND];
__device__ float g_wself[NND];
__device__ float g_Weff [HD * HD];             // folded GCN weight (layers 1,2)

// ---------------- helpers ----------------
__device__ __forceinline__ void red_add_v4(float* p, float4 v) {
    asm volatile("red.global.add.v4.f32 [%0], {%1,%2,%3,%4};"
                 :: "l"(p), "f"(v.x), "f"(v.y), "f"(v.z), "f"(v.w) : "memory");
}

// ---------------- degree / norm ----------------
__global__ void k_deg_init() {
    int i = blockIdx.x * blockDim.x + threadIdx.x;
    if (i < NND) g_deg[i] = 1;                  // appended self loop
}
__global__ void k_deg_count(const int* __restrict__ row, int E) {
    int e = blockIdx.x * blockDim.x + threadIdx.x;
    if (e < E) atomicAdd(&g_deg[row[e]], 1);
}
__global__ void k_dinv() {
    int i = blockIdx.x * blockDim.x + threadIdx.x;
    if (i < NND) g_dinv[i] = rsqrtf((float)g_deg[i]);
}

// ---------------- weight fold: Weff = W[:128] + W[128:] ----------------
__global__ void k_fold(const float* __restrict__ W) {
    int t = blockIdx.x * blockDim.x + threadIdx.x;
    if (t < HD * HD) g_Weff[t] = W[t] + W[t + HD * HD];
}

// ---------------- SGEMM: C[M,128] = A[M,128] @ B[128,128] (+bias) ----------------
#define BM 128
#define BN 128
#define BK 16
__global__ __launch_bounds__(256) void k_gemm(const float* __restrict__ A,
                                              const float* __restrict__ B,
                                              const float* __restrict__ bias,
                                              float* __restrict__ C, int M) {
    __shared__ float As[BK][BM + 4];
    __shared__ float Bs[BK][BN + 4];
    int tid = threadIdx.x;
    int tx = tid & 15, ty = tid >> 4;
    int r0 = ty * 8, c0 = tx * 8;
    int gRow0 = blockIdx.x * BM;
    float acc[8][8];
#pragma unroll
    for (int i = 0; i < 8; i++)
#pragma unroll
        for (int j = 0; j < 8; j++) acc[i][j] = 0.f;

    for (int kk = 0; kk < 128; kk += BK) {
        // A tile: 128 rows x 16 k, stored transposed As[k][row]
#pragma unroll
        for (int it = 0; it < 2; it++) {
            int idx = tid + it * 256;      // 0..511
            int row = idx >> 2;            // 0..127
            int kq  = idx & 3;             // float4 slot in k
            float4 v = make_float4(0.f, 0.f, 0.f, 0.f);
            int gr = gRow0 + row;
            if (gr < M) v = *(const float4*)(A + (size_t)gr * 128 + kk + kq * 4);
            As[kq * 4 + 0][row] = v.x;
            As[kq * 4 + 1][row] = v.y;
            As[kq * 4 + 2][row] = v.z;
            As[kq * 4 + 3][row] = v.w;
        }
        // B tile: 16 x 128 direct copy
#pragma unroll
        for (int it = 0; it < 2; it++) {
            int idx = tid + it * 256;
            int k  = idx >> 5;             // 0..15
            int cq = idx & 31;             // float4 col slot
            float4 v = *(const float4*)(B + (size_t)(kk + k) * 128 + cq * 4);
            *(float4*)(&Bs[k][cq * 4]) = v;
        }
        __syncthreads();
#pragma unroll
        for (int k = 0; k < BK; k++) {
            float a[8], b[8];
#pragma unroll
            for (int i = 0; i < 8; i++) a[i] = As[k][r0 + i];
            float4 b0 = *(float4*)(&Bs[k][c0]);
            float4 b1 = *(float4*)(&Bs[k][c0 + 4]);
            b[0] = b0.x; b[1] = b0.y; b[2] = b0.z; b[3] = b0.w;
            b[4] = b1.x; b[5] = b1.y; b[6] = b1.z; b[7] = b1.w;
#pragma unroll
            for (int i = 0; i < 8; i++)
#pragma unroll
                for (int j = 0; j < 8; j++) acc[i][j] += a[i] * b[j];
        }
        __syncthreads();
    }
    float badd[8];
#pragma unroll
    for (int j = 0; j < 8; j++) badd[j] = bias ? bias[c0 + j] : 0.f;
#pragma unroll
    for (int i = 0; i < 8; i++) {
        int gr = gRow0 + r0 + i;
        if (gr < M) {
            float4 o0 = make_float4(acc[i][0] + badd[0], acc[i][1] + badd[1],
                                    acc[i][2] + badd[2], acc[i][3] + badd[3]);
            float4 o1 = make_float4(acc[i][4] + badd[4], acc[i][5] + badd[5],
                                    acc[i][6] + badd[6], acc[i][7] + badd[7]);
            *(float4*)(C + (size_t)gr * 128 + c0)     = o0;
            *(float4*)(C + (size_t)gr * 128 + c0 + 4) = o1;
        }
    }
}

// ---------------- GCN ----------------
__global__ void k_accinit() {   // appended self loop: acc = xw * dinv^2
    int i = blockIdx.x * blockDim.x + threadIdx.x;
    if (i < NND * HD) {
        float d = g_dinv[i >> 7];
        g_bufACC[i] = g_bufXW[i] * d * d;
    }
}
__global__ void k_gcn_scatter(const int* __restrict__ row,
                              const int* __restrict__ col, int E) {
    int w = (blockIdx.x * blockDim.x + threadIdx.x) >> 5;
    int lane = threadIdx.x & 31;
    if (w >= E) return;
    int r = row[w], c = col[w];
    float nrm = g_dinv[r] * g_dinv[c];
    float4 v = *(const float4*)(g_bufXW + (size_t)c * HD + lane * 4);
    v.x *= nrm; v.y *= nrm; v.z *= nrm; v.w *= nrm;
    red_add_v4(g_bufACC + (size_t)r * HD + lane * 4, v);
}
__global__ void k_relu_bias(const float* __restrict__ bias) {
    int i = blockIdx.x * blockDim.x + threadIdx.x;
    if (i < NND * HD) g_bufACC[i] = fmaxf(g_bufACC[i] + bias[i & 127], 0.f);
}

// ---------------- GAT ----------------
__global__ void k_self() {   // self alpha = |hh|^2 (leaky no-op, >=0); init amax
    int w = (blockIdx.x * blockDim.x + threadIdx.x) >> 5;
    int lane = threadIdx.x & 31;
    if (w >= NND) return;
    float4 a = *(const float4*)(g_bufHH + (size_t)w * HD + lane * 4);
    float s = a.x * a.x + a.y * a.y + a.z * a.z + a.w * a.w;
#pragma unroll
    for (int o = 16; o; o >>= 1) s += __shfl_xor_sync(0xffffffffu, s, o);
    if (lane == 0) { g_self[w] = s; g_amax[w] = s; }
}
__global__ void k_alpha(const int* __restrict__ row,
                        const int* __restrict__ col, int E) {
    int w = (blockIdx.x * blockDim.x + threadIdx.x) >> 5;
    int lane = threadIdx.x & 31;
    if (w >= E) return;
    int r = row[w], c = col[w];
    if (r == c) {                       // original self loop: masked out
        if (lane == 0) g_alpha[w] = -CUDART_INF_F;
        return;
    }
    float4 a = *(const float4*)(g_bufHH + (size_t)r * HD + lane * 4);
    float4 b = *(const float4*)(g_bufHH + (size_t)c * HD + lane * 4);
    float s = a.x * b.x + a.y * b.y + a.z * b.z + a.w * b.w;
#pragma unroll
    for (int o = 16; o; o >>= 1) s += __shfl_xor_sync(0xffffffffu, s, o);
    float al = (s > 0.f) ? s : 0.2f * s;
    if (lane == 0) {
        g_alpha[w] = al;
        // amax init >= 0, so int-compare atomicMax is order-correct; negatives can't win
        if (al > 0.f) atomicMax((int*)&g_amax[r], __float_as_int(al));
    }
}
__global__ void k_denominit() {
    int i = blockIdx.x * blockDim.x + threadIdx.x;
    if (i < NND) g_denom[i] = expf(g_self[i] - g_amax[i]);
}
__global__ void k_expsum(const int* __restrict__ row, int E) {
    int e = blockIdx.x * blockDim.x + threadIdx.x;
    if (e >= E) return;
    int r = row[e];
    float a = expf(g_alpha[e] - g_amax[r]);   // -inf -> 0
    g_alpha[e] = a;
    if (a > 0.f) atomicAdd(&g_denom[r], a);
}
__global__ void k_wself() {
    int i = blockIdx.x * blockDim.x + threadIdx.x;
    if (i < NND)
        g_wself[i] = expf(g_self[i] - g_amax[i]) / fmaxf(g_denom[i], 1e-16f);
}
__global__ void k_outinit() {   // appended self-loop contribution
    int i = blockIdx.x * blockDim.x + threadIdx.x;
    if (i < NND * HD) g_bufOUT[i] = g_bufHH[i] * g_wself[i >> 7];
}
__global__ void k_gat_scatter(const int* __restrict__ row,
                              const int* __restrict__ col, int E) {
    int w = (blockIdx.x * blockDim.x + threadIdx.x) >> 5;
    int lane = threadIdx.x & 31;
    if (w >= E) return;
    float a = g_alpha[w];
    if (a == 0.f) return;                    // invalid or fully-underflowed edge
    int r = row[w], c = col[w];
    float wgt = a / fmaxf(g_denom[r], 1e-16f);
    float4 v = *(const float4*)(g_bufHH + (size_t)c * HD + lane * 4);
    v.x *= wgt; v.y *= wgt; v.z *= wgt; v.w *= wgt;
    red_add_v4(g_bufOUT + (size_t)r * HD + lane * 4, v);
}

// ---------------- final mean pool ----------------
__global__ void k_zero_out(float* out) {
    int t = threadIdx.x;
    if (t < 2 * HD) out[t] = 0.f;
}
__global__ void k_mean(float* __restrict__ out) {
    int col = threadIdx.x;                    // 128 threads
    float s = 0.f;
    for (int i = blockIdx.x; i < NND; i += gridDim.x)
        s += g_bufOUT[(size_t)i * HD + col];
    s *= (1.0f / NND);
    atomicAdd(&out[col], s);
    atomicAdd(&out[col + HD], s);
}

// ---------------- launch ----------------
extern "C" void kernel_launch(void* const* d_in, const int* in_sizes, int n_in,
                              void* d_out, int out_size) {
    const float* x   = (const float*)d_in[0];
    const int*   ei  = (const int*)d_in[1];     // JAX default x64 disabled -> int32
    int E = in_sizes[1] / 2;
    const int* row = ei;
    const int* col = ei + E;
    const float* Wg[3] = {(const float*)d_in[2], (const float*)d_in[6],  (const float*)d_in[10]};
    const float* bg[3] = {(const float*)d_in[3], (const float*)d_in[7],  (const float*)d_in[11]};
    const float* Wa[3] = {(const float*)d_in[4], (const float*)d_in[8],  (const float*)d_in[12]};
    const float* ba[3] = {(const float*)d_in[5], (const float*)d_in[9],  (const float*)d_in[13]};
    float* out = (float*)d_out;

    float *pXW, *pACC, *pHH, *pOUT, *pWeff;
    cudaGetSymbolAddress((void**)&pXW,  g_bufXW);
    cudaGetSymbolAddress((void**)&pACC, g_bufACC);
    cudaGetSymbolAddress((void**)&pHH,  g_bufHH);
    cudaGetSymbolAddress((void**)&pOUT, g_bufOUT);
    cudaGetSymbolAddress((void**)&pWeff, g_Weff);

    const int TB = 256;
    int gN   = (NND + TB - 1) / TB;
    int gE   = (E + TB - 1) / TB;
    int gNH  = (NND * HD + TB - 1) / TB;
    int gEw  = (E + 7) / 8;       // warp-per-edge, 8 warps/block
    int gNw  = (NND + 7) / 8;     // warp-per-node
    int gGemm = (NND + BM - 1) / BM;

    k_deg_init<<<gN, TB>>>();
    k_deg_count<<<gE, TB>>>(row, E);
    k_dinv<<<gN, TB>>>();

    const float* cur = x;
    for (int l = 0; l < 3; l++) {
        const float* Wg_use = Wg[l];
        if (l > 0) { k_fold<<<64, TB>>>(Wg[l]); Wg_use = pWeff; }
        // GCN
        k_gemm<<<gGemm, TB>>>(cur, Wg_use, nullptr, pXW, NND);
        k_accinit<<<gNH, TB>>>();
        k_gcn_scatter<<<gEw, TB>>>(row, col, E);
        k_relu_bias<<<gNH, TB>>>(bg[l]);
        // GAT
        k_gemm<<<gGemm, TB>>>(pACC, Wa[l], ba[l], pHH, NND);
        k_self<<<gNw, TB>>>();
        k_alpha<<<gEw, TB>>>(row, col, E);
        k_denominit<<<gN, TB>>>();
        k_expsum<<<gE, TB>>>(row, E);
        k_wself<<<gN, TB>>>();
        k_outinit<<<gNH, TB>>>();
        k_gat_scatter<<<gEw, TB>>>(row, col, E);
        cur = pOUT;
    }
    k_zero_out<<<1, TB>>>(out);
    k_mean<<<512, HD>>>(out);
}

// round 3
// speedup vs baseline: 1.6921x; 1.6921x over previous
#include <cuda_runtime.h>
#include <cstdint>
#include <math_constants.h>

#define NND 40000
#define HD  128
#define EED 640000

// ---------------- scratch (device globals: allocation-free) ----------------
__device__ float g_bufXW [(size_t)NND * HD];   // GEMM out (GCN xw) / GAT features
__device__ float g_bufACC[(size_t)NND * HD];   // relu(GCN) output
__device__ float g_bufHH [(size_t)NND * HD];   // GAT transformed features
__device__ float g_bufOUT[(size_t)NND * HD];   // GAT result (next layer input)
__device__ int   g_deg   [NND];                // degree incl. appended self loop
__device__ float g_dinv  [NND];
__device__ int   g_rowptr[NND];
__device__ int   g_cursor[NND];
__device__ int   g_csrcol[EED];
__device__ float g_alpha [EED];                // per-edge alpha (CSR order)
__device__ float g_Weff  [HD * HD];            // folded GCN weight (layers 1,2)

// ---------------- degree / norm ----------------
__global__ void k_deg_init() {
    int i = blockIdx.x * blockDim.x + threadIdx.x;
    if (i < NND) g_deg[i] = 1;                  // appended self loop
}
__global__ void k_deg_count(const int* __restrict__ row, int E) {
    int e = blockIdx.x * blockDim.x + threadIdx.x;
    if (e < E) atomicAdd(&g_deg[row[e]], 1);
}
__global__ void k_dinv() {
    int i = blockIdx.x * blockDim.x + threadIdx.x;
    if (i < NND) g_dinv[i] = rsqrtf((float)g_deg[i]);
}

// ---------------- CSR build ----------------
// Single block, 1024 threads, 40 nodes/thread: exclusive scan of (deg-1).
__global__ __launch_bounds__(1024) void k_scan() {
    __shared__ int part[1024];
    int t = threadIdx.x;
    int start = t * 40;
    int end = min(start + 40, NND);
    int s = 0;
    for (int i = start; i < end; i++) s += g_deg[i] - 1;
    part[t] = s;
    __syncthreads();
    // inclusive scan over partials
    for (int off = 1; off < 1024; off <<= 1) {
        int v = (t >= off) ? part[t - off] : 0;
        __syncthreads();
        part[t] += v;
        __syncthreads();
    }
    int run = (t > 0) ? part[t - 1] : 0;
    for (int i = start; i < end; i++) {
        g_rowptr[i] = run;
        g_cursor[i] = run;
        run += g_deg[i] - 1;
    }
}
__global__ void k_fill(const int* __restrict__ row, const int* __restrict__ col, int E) {
    int e = blockIdx.x * blockDim.x + threadIdx.x;
    if (e >= E) return;
    int r = row[e];
    int pos = atomicAdd(&g_cursor[r], 1);
    g_csrcol[pos] = col[e];
}

// ---------------- weight fold: Weff = W[:128] + W[128:] ----------------
__global__ void k_fold(const float* __restrict__ W) {
    int t = blockIdx.x * blockDim.x + threadIdx.x;
    if (t < HD * HD) g_Weff[t] = W[t] + W[t + HD * HD];
}

// ---------------- SGEMM: C[M,128] = A[M,128] @ B[128,128] (+bias) ----------------
#define BM 128
#define BN 128
#define BK 16
__global__ __launch_bounds__(256) void k_gemm(const float* __restrict__ A,
                                              const float* __restrict__ B,
                                              const float* __restrict__ bias,
                                              float* __restrict__ C, int M) {
    __shared__ float As[BK][BM + 4];
    __shared__ float Bs[BK][BN + 4];
    int tid = threadIdx.x;
    int tx = tid & 15, ty = tid >> 4;
    int r0 = ty * 8, c0 = tx * 8;
    int gRow0 = blockIdx.x * BM;
    float acc[8][8];
#pragma unroll
    for (int i = 0; i < 8; i++)
#pragma unroll
        for (int j = 0; j < 8; j++) acc[i][j] = 0.f;

    for (int kk = 0; kk < 128; kk += BK) {
#pragma unroll
        for (int it = 0; it < 2; it++) {
            int idx = tid + it * 256;
            int row = idx >> 2;
            int kq  = idx & 3;
            float4 v = make_float4(0.f, 0.f, 0.f, 0.f);
            int gr = gRow0 + row;
            if (gr < M) v = *(const float4*)(A + (size_t)gr * 128 + kk + kq * 4);
            As[kq * 4 + 0][row] = v.x;
            As[kq * 4 + 1][row] = v.y;
            As[kq * 4 + 2][row] = v.z;
            As[kq * 4 + 3][row] = v.w;
        }
#pragma unroll
        for (int it = 0; it < 2; it++) {
            int idx = tid + it * 256;
            int k  = idx >> 5;
            int cq = idx & 31;
            float4 v = *(const float4*)(B + (size_t)(kk + k) * 128 + cq * 4);
            *(float4*)(&Bs[k][cq * 4]) = v;
        }
        __syncthreads();
#pragma unroll
        for (int k = 0; k < BK; k++) {
            float a[8], b[8];
#pragma unroll
            for (int i = 0; i < 8; i++) a[i] = As[k][r0 + i];
            float4 b0 = *(float4*)(&Bs[k][c0]);
            float4 b1 = *(float4*)(&Bs[k][c0 + 4]);
            b[0] = b0.x; b[1] = b0.y; b[2] = b0.z; b[3] = b0.w;
            b[4] = b1.x; b[5] = b1.y; b[6] = b1.z; b[7] = b1.w;
#pragma unroll
            for (int i = 0; i < 8; i++)
#pragma unroll
                for (int j = 0; j < 8; j++) acc[i][j] += a[i] * b[j];
        }
        __syncthreads();
    }
    float badd[8];
#pragma unroll
    for (int j = 0; j < 8; j++) badd[j] = bias ? bias[c0 + j] : 0.f;
#pragma unroll
    for (int i = 0; i < 8; i++) {
        int gr = gRow0 + r0 + i;
        if (gr < M) {
            float4 o0 = make_float4(acc[i][0] + badd[0], acc[i][1] + badd[1],
                                    acc[i][2] + badd[2], acc[i][3] + badd[3]);
            float4 o1 = make_float4(acc[i][4] + badd[4], acc[i][5] + badd[5],
                                    acc[i][6] + badd[6], acc[i][7] + badd[7]);
            *(float4*)(C + (size_t)gr * 128 + c0)     = o0;
            *(float4*)(C + (size_t)gr * 128 + c0 + 4) = o1;
        }
    }
}

// ---------------- fused GCN (warp per node, CSR) ----------------
__global__ __launch_bounds__(256) void k_gcn(const float* __restrict__ bias) {
    int r = (blockIdx.x * blockDim.x + threadIdx.x) >> 5;
    int lane = threadIdx.x & 31;
    if (r >= NND) return;
    int beg = g_rowptr[r];
    int cnt = g_deg[r] - 1;
    float dr = g_dinv[r];
    const float* xw = g_bufXW;
    float4 acc = *(const float4*)(xw + (size_t)r * HD + lane * 4);  // appended self loop
    float dr2 = dr * dr;
    acc.x *= dr2; acc.y *= dr2; acc.z *= dr2; acc.w *= dr2;
    for (int j = 0; j < cnt; j++) {
        int c = g_csrcol[beg + j];
        float nrm = dr * g_dinv[c];
        float4 v = *(const float4*)(xw + (size_t)c * HD + lane * 4);
        acc.x += v.x * nrm; acc.y += v.y * nrm;
        acc.z += v.z * nrm; acc.w += v.w * nrm;
    }
    float4 b = *(const float4*)(bias + lane * 4);
    acc.x = fmaxf(acc.x + b.x, 0.f);
    acc.y = fmaxf(acc.y + b.y, 0.f);
    acc.z = fmaxf(acc.z + b.z, 0.f);
    acc.w = fmaxf(acc.w + b.w, 0.f);
    *(float4*)(g_bufACC + (size_t)r * HD + lane * 4) = acc;
}

// ---------------- fused GAT (warp per node, CSR) ----------------
__device__ __forceinline__ float warp_sum(float s) {
#pragma unroll
    for (int o = 16; o; o >>= 1) s += __shfl_xor_sync(0xffffffffu, s, o);
    return s;
}
__global__ __launch_bounds__(256) void k_gat() {
    int r = (blockIdx.x * blockDim.x + threadIdx.x) >> 5;
    int lane = threadIdx.x & 31;
    if (r >= NND) return;
    int beg = g_rowptr[r];
    int cnt = g_deg[r] - 1;
    const float* hh = g_bufHH;
    float4 hr = *(const float4*)(hh + (size_t)r * HD + lane * 4);
    float selfdot = warp_sum(hr.x * hr.x + hr.y * hr.y + hr.z * hr.z + hr.w * hr.w);
    float amax = selfdot;                       // >= 0, dominates masked edges
    // pass 1: dots + raw alpha
    for (int j = 0; j < cnt; j++) {
        int c = g_csrcol[beg + j];
        if (c == r) {                           // original self loop: masked
            if (lane == 0) g_alpha[beg + j] = -CUDART_INF_F;
            continue;
        }
        float4 hc = *(const float4*)(hh + (size_t)c * HD + lane * 4);
        float d = warp_sum(hr.x * hc.x + hr.y * hc.y + hr.z * hc.z + hr.w * hc.w);
        float al = (d > 0.f) ? d : 0.2f * d;
        amax = fmaxf(amax, al);
        if (lane == 0) g_alpha[beg + j] = al;
    }
    __syncwarp();
    // pass 2: exp + denom (parallel across lanes)
    float selfexp = expf(selfdot - amax);
    float part = 0.f;
    for (int j = lane; j < cnt; j += 32) {
        float a = expf(g_alpha[beg + j] - amax);  // -inf -> 0
        g_alpha[beg + j] = a;
        part += a;
    }
    float denom = selfexp + warp_sum(part);
    float inv = 1.f / fmaxf(denom, 1e-16f);
    __syncwarp();
    // pass 3: weighted aggregation
    float ws = selfexp * inv;
    float4 acc = make_float4(hr.x * ws, hr.y * ws, hr.z * ws, hr.w * ws);
    for (int j = 0; j < cnt; j++) {
        float a = g_alpha[beg + j];
        if (a == 0.f) continue;
        int c = g_csrcol[beg + j];
        float w = a * inv;
        float4 hc = *(const float4*)(hh + (size_t)c * HD + lane * 4);
        acc.x += hc.x * w; acc.y += hc.y * w;
        acc.z += hc.z * w; acc.w += hc.w * w;
    }
    *(float4*)(g_bufOUT + (size_t)r * HD + lane * 4) = acc;
}

// ---------------- final mean pool ----------------
__global__ void k_zero_out(float* out) {
    int t = threadIdx.x;
    if (t < 2 * HD) out[t] = 0.f;
}
__global__ void k_mean(float* __restrict__ out) {
    int col = threadIdx.x;                    // 128 threads
    float s = 0.f;
    for (int i = blockIdx.x; i < NND; i += gridDim.x)
        s += g_bufOUT[(size_t)i * HD + col];
    s *= (1.0f / NND);
    atomicAdd(&out[col], s);
    atomicAdd(&out[col + HD], s);
}

// ---------------- launch ----------------
extern "C" void kernel_launch(void* const* d_in, const int* in_sizes, int n_in,
                              void* d_out, int out_size) {
    const float* x   = (const float*)d_in[0];
    const int*   ei  = (const int*)d_in[1];     // int32 (JAX x64 disabled)
    int E = in_sizes[1] / 2;
    const int* row = ei;
    const int* col = ei + E;
    const float* Wg[3] = {(const float*)d_in[2], (const float*)d_in[6],  (const float*)d_in[10]};
    const float* bg[3] = {(const float*)d_in[3], (const float*)d_in[7],  (const float*)d_in[11]};
    const float* Wa[3] = {(const float*)d_in[4], (const float*)d_in[8],  (const float*)d_in[12]};
    const float* ba[3] = {(const float*)d_in[5], (const float*)d_in[9],  (const float*)d_in[13]};
    float* out = (float*)d_out;

    float *pXW, *pACC, *pHH, *pOUT, *pWeff;
    cudaGetSymbolAddress((void**)&pXW,  g_bufXW);
    cudaGetSymbolAddress((void**)&pACC, g_bufACC);
    cudaGetSymbolAddress((void**)&pHH,  g_bufHH);
    cudaGetSymbolAddress((void**)&pOUT, g_bufOUT);
    cudaGetSymbolAddress((void**)&pWeff, g_Weff);

    const int TB = 256;
    int gN  = (NND + TB - 1) / TB;
    int gE  = (E + TB - 1) / TB;
    int gNw = (NND + 7) / 8;       // warp-per-node, 8 warps/block
    int gGemm = (NND + BM - 1) / BM;

    k_deg_init<<<gN, TB>>>();
    k_deg_count<<<gE, TB>>>(row, E);
    k_dinv<<<gN, TB>>>();
    k_scan<<<1, 1024>>>();
    k_fill<<<gE, TB>>>(row, col, E);

    const float* cur = x;
    for (int l = 0; l < 3; l++) {
        const float* Wg_use = Wg[l];
        if (l > 0) { k_fold<<<64, TB>>>(Wg[l]); Wg_use = pWeff; }
        k_gemm<<<gGemm, TB>>>(cur, Wg_use, nullptr, pXW, NND);
        k_gcn<<<gNw, TB>>>(bg[l]);
        k_gemm<<<gGemm, TB>>>(pACC, Wa[l], ba[l], pHH, NND);
        k_gat<<<gNw, TB>>>();
        cur = pOUT;
    }
    k_zero_out<<<1, TB>>>(out);
    k_mean<<<512, HD>>>(out);
}

// round 4
// speedup vs baseline: 1.9095x; 1.1285x over previous
#include <cuda_runtime.h>
#include <cstdint>
#include <math_constants.h>

#define NND 40000
#define HD  128
#define EED 640000

// ---------------- scratch (device globals: allocation-free) ----------------
__device__ float g_bufXW [(size_t)NND * HD];   // GEMM out (GCN xw) / GAT features
__device__ float g_bufACC[(size_t)NND * HD];   // relu(GCN) output
__device__ float g_bufHH [(size_t)NND * HD];   // GAT transformed features
__device__ float g_bufOUT[(size_t)NND * HD];   // GAT result (next layer input)
__device__ int   g_deg   [NND];                // degree incl. appended self loop
__device__ float g_dinv  [NND];
__device__ int   g_rowptr[NND];
__device__ int   g_cursor[NND];
__device__ int   g_rowtmp[NND];
__device__ int   g_bsum  [256];
__device__ int   g_boff  [256];
__device__ int   g_csrcol[EED];
__device__ float g_alpha [EED];                // per-edge alpha (CSR order)
__device__ float g_Weff  [HD * HD];            // folded GCN weight (layers 1,2)

// ---------------- degree / norm ----------------
__global__ void k_deg_init() {
    int i = blockIdx.x * blockDim.x + threadIdx.x;
    if (i < NND) g_deg[i] = 1;                  // appended self loop
}
__global__ void k_deg_count(const int* __restrict__ row, int E) {
    int e = blockIdx.x * blockDim.x + threadIdx.x;
    if (e < E) atomicAdd(&g_deg[row[e]], 1);
}
__global__ void k_dinv() {
    int i = blockIdx.x * blockDim.x + threadIdx.x;
    if (i < NND) g_dinv[i] = rsqrtf((float)g_deg[i]);
}

// ---------------- hierarchical exclusive scan of (deg-1) ----------------
__global__ __launch_bounds__(256) void k_scanA() {
    __shared__ int sm[256];
    int tx = threadIdx.x;
    int i = blockIdx.x * 256 + tx;
    int v = (i < NND) ? g_deg[i] - 1 : 0;
    sm[tx] = v;
    __syncthreads();
#pragma unroll
    for (int off = 1; off < 256; off <<= 1) {
        int p = (tx >= off) ? sm[tx - off] : 0;
        __syncthreads();
        sm[tx] += p;
        __syncthreads();
    }
    if (i < NND) g_rowtmp[i] = sm[tx] - v;      // exclusive within block
    if (tx == 255) g_bsum[blockIdx.x] = sm[255];
}
__global__ __launch_bounds__(256) void k_scanB(int nb) {
    __shared__ int sm[256];
    int tx = threadIdx.x;
    int v = (tx < nb) ? g_bsum[tx] : 0;
    sm[tx] = v;
    __syncthreads();
#pragma unroll
    for (int off = 1; off < 256; off <<= 1) {
        int p = (tx >= off) ? sm[tx - off] : 0;
        __syncthreads();
        sm[tx] += p;
        __syncthreads();
    }
    g_boff[tx] = sm[tx] - v;                    // exclusive block offsets
}
__global__ void k_scanC() {
    int i = blockIdx.x * blockDim.x + threadIdx.x;
    if (i < NND) {
        int rp = g_rowtmp[i] + g_boff[i >> 8];
        g_rowptr[i] = rp;
        g_cursor[i] = rp;
    }
}
__global__ void k_fill(const int* __restrict__ row, const int* __restrict__ col, int E) {
    int e = blockIdx.x * blockDim.x + threadIdx.x;
    if (e >= E) return;
    int r = row[e];
    int pos = atomicAdd(&g_cursor[r], 1);
    g_csrcol[pos] = col[e];
}

// ---------------- weight fold: Weff = W[:128] + W[128:] ----------------
__global__ void k_fold(const float* __restrict__ W) {
    int t = blockIdx.x * blockDim.x + threadIdx.x;
    if (t < HD * HD) g_Weff[t] = W[t] + W[t + HD * HD];
}

// ---------------- TF32 tensor-core GEMM: C[M,128] = A[M,128] @ B[128,128] (+bias) ----
// 256 threads (8 warps in 2x4), block tile 128x128, K chunked by 32.
// smem holds fragment-permuted tf32 tiles: one LDS.128 per A-atom, LDS.64 per B-atom.
__device__ __forceinline__ uint32_t f2tf32(float f) {
    uint32_t u;
    asm("cvt.rna.tf32.f32 %0, %1;" : "=r"(u) : "f"(f));
    return u;
}
__device__ __forceinline__ void mma_tf32(float* d, const uint32_t* a, const uint32_t* b) {
    asm volatile(
        "mma.sync.aligned.m16n8k8.row.col.f32.tf32.tf32.f32 "
        "{%0,%1,%2,%3}, {%4,%5,%6,%7}, {%8,%9}, {%0,%1,%2,%3};"
        : "+f"(d[0]), "+f"(d[1]), "+f"(d[2]), "+f"(d[3])
        : "r"(a[0]), "r"(a[1]), "r"(a[2]), "r"(a[3]), "r"(b[0]), "r"(b[1]));
}
__global__ __launch_bounds__(256) void k_gemm_tf32(const float* __restrict__ A,
                                                   const float* __restrict__ B,
                                                   const float* __restrict__ bias,
                                                   float* __restrict__ C, int M) {
    __shared__ uint32_t Asp[32 * 128];   // atom (ki*8+mi): 128 tf32, lane*4+j
    __shared__ uint32_t Bsp[64 * 64];    // atom (ki*16+ni): 64 tf32, lane*2+j
    int tid = threadIdx.x;
    int lane = tid & 31;
    int w = tid >> 5;
    int wm = w >> 2, wn = w & 3;         // warp grid 2(m) x 4(n)
    int gRow0 = blockIdx.x * 128;
    float acc[4][4][4];
#pragma unroll
    for (int i = 0; i < 4; i++)
#pragma unroll
        for (int t = 0; t < 4; t++)
#pragma unroll
            for (int u = 0; u < 4; u++) acc[i][t][u] = 0.f;

    for (int kk = 0; kk < 128; kk += 32) {
        // ---- stage A chunk [128 rows x 32 k] permuted ----
#pragma unroll
        for (int q = 0; q < 4; q++) {
            int fid = tid + q * 256;          // 0..1023 float4 units
            int row = fid >> 3;               // 0..127
            int c4  = fid & 7;                // 0..7
            int gr = gRow0 + row;
            float4 v = make_float4(0.f, 0.f, 0.f, 0.f);
            if (gr < M) v = *(const float4*)(A + (size_t)gr * 128 + kk + c4 * 4);
            float vv[4] = {v.x, v.y, v.z, v.w};
            int mi = row >> 4, r = row & 15;
#pragma unroll
            for (int u = 0; u < 4; u++) {
                int cl = c4 * 4 + u;          // local k 0..31
                int ki = cl >> 3, cc = cl & 7;
                int ln = ((r & 7) << 2) | (cc & 3);
                int j  = (r >> 3) | ((cc >> 2) << 1);
                Asp[(ki * 8 + mi) * 128 + ln * 4 + j] = f2tf32(vv[u]);
            }
        }
        // ---- stage B chunk [32 k x 128 n] permuted ----
#pragma unroll
        for (int q = 0; q < 4; q++) {
            int fid = tid + q * 256;
            int kr = fid >> 5;                // local k 0..31
            int c4 = fid & 31;                // float4 col
            float4 v = *(const float4*)(B + (size_t)(kk + kr) * 128 + c4 * 4);
            float vv[4] = {v.x, v.y, v.z, v.w};
            int ki = kr >> 3, r = kr & 7;
#pragma unroll
            for (int u = 0; u < 4; u++) {
                int n = c4 * 4 + u;
                int ni = n >> 3, cn = n & 7;
                int ln = (cn << 2) | (r & 3);
                int j  = r >> 2;
                Bsp[(ki * 16 + ni) * 64 + ln * 2 + j] = f2tf32(vv[u]);
            }
        }
        __syncthreads();
        // ---- compute: 4 k-steps of k8 ----
#pragma unroll
        for (int ki = 0; ki < 4; ki++) {
            uint32_t af[4][4], bf[4][2];
#pragma unroll
            for (int i = 0; i < 4; i++) {
                uint4 a4 = *(const uint4*)(&Asp[(ki * 8 + wm * 4 + i) * 128 + lane * 4]);
                af[i][0] = a4.x; af[i][1] = a4.y; af[i][2] = a4.z; af[i][3] = a4.w;
            }
#pragma unroll
            for (int t = 0; t < 4; t++) {
                uint2 b2 = *(const uint2*)(&Bsp[(ki * 16 + wn * 4 + t) * 64 + lane * 2]);
                bf[t][0] = b2.x; bf[t][1] = b2.y;
            }
#pragma unroll
            for (int i = 0; i < 4; i++)
#pragma unroll
                for (int t = 0; t < 4; t++) mma_tf32(acc[i][t], af[i], bf[t]);
        }
        __syncthreads();
    }
    // ---- epilogue ----
    int g = lane >> 2, t4 = lane & 3;
#pragma unroll
    for (int i = 0; i < 4; i++) {
#pragma unroll
        for (int t = 0; t < 4; t++) {
            int col = (wn * 4 + t) * 8 + 2 * t4;
            float b0 = bias ? bias[col] : 0.f;
            float b1 = bias ? bias[col + 1] : 0.f;
            int row0 = gRow0 + (wm * 4 + i) * 16 + g;
            int row1 = row0 + 8;
            if (row0 < M) {
                float2 o = make_float2(acc[i][t][0] + b0, acc[i][t][1] + b1);
                *(float2*)(C + (size_t)row0 * 128 + col) = o;
            }
            if (row1 < M) {
                float2 o = make_float2(acc[i][t][2] + b0, acc[i][t][3] + b1);
                *(float2*)(C + (size_t)row1 * 128 + col) = o;
            }
        }
    }
}

// ---------------- fused GCN (warp per node, CSR) ----------------
__global__ __launch_bounds__(256) void k_gcn(const float* __restrict__ bias) {
    int r = (blockIdx.x * blockDim.x + threadIdx.x) >> 5;
    int lane = threadIdx.x & 31;
    if (r >= NND) return;
    int beg = g_rowptr[r];
    int cnt = g_deg[r] - 1;
    float dr = g_dinv[r];
    const float* xw = g_bufXW;
    float4 acc = *(const float4*)(xw + (size_t)r * HD + lane * 4);  // appended self loop
    float dr2 = dr * dr;
    acc.x *= dr2; acc.y *= dr2; acc.z *= dr2; acc.w *= dr2;
    for (int j = 0; j < cnt; j++) {
        int c = g_csrcol[beg + j];
        float nrm = dr * g_dinv[c];
        float4 v = *(const float4*)(xw + (size_t)c * HD + lane * 4);
        acc.x += v.x * nrm; acc.y += v.y * nrm;
        acc.z += v.z * nrm; acc.w += v.w * nrm;
    }
    float4 b = *(const float4*)(bias + lane * 4);
    acc.x = fmaxf(acc.x + b.x, 0.f);
    acc.y = fmaxf(acc.y + b.y, 0.f);
    acc.z = fmaxf(acc.z + b.z, 0.f);
    acc.w = fmaxf(acc.w + b.w, 0.f);
    *(float4*)(g_bufACC + (size_t)r * HD + lane * 4) = acc;
}

// ---------------- fused GAT (warp per node, CSR) ----------------
__device__ __forceinline__ float warp_sum(float s) {
#pragma unroll
    for (int o = 16; o; o >>= 1) s += __shfl_xor_sync(0xffffffffu, s, o);
    return s;
}
__global__ __launch_bounds__(256) void k_gat() {
    int r = (blockIdx.x * blockDim.x + threadIdx.x) >> 5;
    int lane = threadIdx.x & 31;
    if (r >= NND) return;
    int beg = g_rowptr[r];
    int cnt = g_deg[r] - 1;
    const float* hh = g_bufHH;
    float4 hr = *(const float4*)(hh + (size_t)r * HD + lane * 4);
    float selfdot = warp_sum(hr.x * hr.x + hr.y * hr.y + hr.z * hr.z + hr.w * hr.w);
    float amax = selfdot;                       // >= 0, dominates masked edges
    for (int j = 0; j < cnt; j++) {
        int c = g_csrcol[beg + j];
        if (c == r) {                           // original self loop: masked
            if (lane == 0) g_alpha[beg + j] = -CUDART_INF_F;
            continue;
        }
        float4 hc = *(const float4*)(hh + (size_t)c * HD + lane * 4);
        float d = warp_sum(hr.x * hc.x + hr.y * hc.y + hr.z * hc.z + hr.w * hc.w);
        float al = (d > 0.f) ? d : 0.2f * d;
        amax = fmaxf(amax, al);
        if (lane == 0) g_alpha[beg + j] = al;
    }
    __syncwarp();
    float selfexp = expf(selfdot - amax);
    float part = 0.f;
    for (int j = lane; j < cnt; j += 32) {
        float a = expf(g_alpha[beg + j] - amax);  // -inf -> 0
        g_alpha[beg + j] = a;
        part += a;
    }
    float denom = selfexp + warp_sum(part);
    float inv = 1.f / fmaxf(denom, 1e-16f);
    __syncwarp();
    float ws = selfexp * inv;
    float4 acc = make_float4(hr.x * ws, hr.y * ws, hr.z * ws, hr.w * ws);
    for (int j = 0; j < cnt; j++) {
        float a = g_alpha[beg + j];
        if (a == 0.f) continue;
        int c = g_csrcol[beg + j];
        float w = a * inv;
        float4 hc = *(const float4*)(hh + (size_t)c * HD + lane * 4);
        acc.x += hc.x * w; acc.y += hc.y * w;
        acc.z += hc.z * w; acc.w += hc.w * w;
    }
    *(float4*)(g_bufOUT + (size_t)r * HD + lane * 4) = acc;
}

// ---------------- final mean pool ----------------
__global__ void k_zero_out(float* out) {
    int t = threadIdx.x;
    if (t < 2 * HD) out[t] = 0.f;
}
__global__ void k_mean(float* __restrict__ out) {
    int col = threadIdx.x;                    // 128 threads
    float s = 0.f;
    for (int i = blockIdx.x; i < NND; i += gridDim.x)
        s += g_bufOUT[(size_t)i * HD + col];
    s *= (1.0f / NND);
    atomicAdd(&out[col], s);
    atomicAdd(&out[col + HD], s);
}

// ---------------- launch ----------------
extern "C" void kernel_launch(void* const* d_in, const int* in_sizes, int n_in,
                              void* d_out, int out_size) {
    const float* x   = (const float*)d_in[0];
    const int*   ei  = (const int*)d_in[1];     // int32 (JAX x64 disabled)
    int E = in_sizes[1] / 2;
    const int* row = ei;
    const int* col = ei + E;
    const float* Wg[3] = {(const float*)d_in[2], (const float*)d_in[6],  (const float*)d_in[10]};
    const float* bg[3] = {(const float*)d_in[3], (const float*)d_in[7],  (const float*)d_in[11]};
    const float* Wa[3] = {(const float*)d_in[4], (const float*)d_in[8],  (const float*)d_in[12]};
    const float* ba[3] = {(const float*)d_in[5], (const float*)d_in[9],  (const float*)d_in[13]};
    float* out = (float*)d_out;

    float *pXW, *pACC, *pHH, *pOUT, *pWeff;
    cudaGetSymbolAddress((void**)&pXW,  g_bufXW);
    cudaGetSymbolAddress((void**)&pACC, g_bufACC);
    cudaGetSymbolAddress((void**)&pHH,  g_bufHH);
    cudaGetSymbolAddress((void**)&pOUT, g_bufOUT);
    cudaGetSymbolAddress((void**)&pWeff, g_Weff);

    const int TB = 256;
    int gN  = (NND + TB - 1) / TB;              // 157
    int gE  = (E + TB - 1) / TB;
    int gNw = (NND + 7) / 8;                    // warp-per-node, 8 warps/block
    int gGemm = (NND + 127) / 128;              // 313

    k_deg_init<<<gN, TB>>>();
    k_deg_count<<<gE, TB>>>(row, E);
    k_dinv<<<gN, TB>>>();
    k_scanA<<<gN, TB>>>();
    k_scanB<<<1, TB>>>(gN);
    k_scanC<<<gN, TB>>>();
    k_fill<<<gE, TB>>>(row, col, E);

    const float* cur = x;
    for (int l = 0; l < 3; l++) {
        const float* Wg_use = Wg[l];
        if (l > 0) { k_fold<<<64, TB>>>(Wg[l]); Wg_use = pWeff; }
        k_gemm_tf32<<<gGemm, TB>>>(cur, Wg_use, nullptr, pXW, NND);
        k_gcn<<<gNw, TB>>>(bg[l]);
        k_gemm_tf32<<<gGemm, TB>>>(pACC, Wa[l], ba[l], pHH, NND);
        k_gat<<<gNw, TB>>>();
        cur = pOUT;
    }
    k_zero_out<<<1, TB>>>(out);
    k_mean<<<512, HD>>>(out);
}

// round 5
// speedup vs baseline: 2.5898x; 1.3563x over previous
#include <cuda_runtime.h>
#include <cstdint>
#include <math_constants.h>

#define NND 40000
#define HD  128
#define EED 640000

// ---------------- scratch (device globals: allocation-free) ----------------
__device__ float    g_bufXW [(size_t)NND * HD];
__device__ float    g_bufACC[(size_t)NND * HD];
__device__ float    g_bufHH [(size_t)NND * HD];
__device__ float    g_bufOUT[(size_t)NND * HD];
__device__ int      g_deg   [NND];
__device__ float    g_dinv  [NND];
__device__ int      g_rowptr[NND];
__device__ int      g_cursor[NND];
__device__ int      g_rowtmp[NND];
__device__ int      g_bsum  [256];
__device__ int      g_boff  [256];
__device__ int      g_csrcol[EED];
__device__ uint32_t g_Bperm [HD * HD];   // tf32 fragment-permuted weight (per layer)

// ---------------- degree / norm ----------------
__global__ void k_deg_init() {
    int i = blockIdx.x * blockDim.x + threadIdx.x;
    if (i < NND) g_deg[i] = 1;
}
__global__ void k_deg_count(const int* __restrict__ row, int E) {
    int e = blockIdx.x * blockDim.x + threadIdx.x;
    if (e < E) atomicAdd(&g_deg[row[e]], 1);
}
__global__ void k_dinv() {
    int i = blockIdx.x * blockDim.x + threadIdx.x;
    if (i < NND) g_dinv[i] = rsqrtf((float)g_deg[i]);
}

// ---------------- hierarchical exclusive scan of (deg-1) ----------------
__global__ __launch_bounds__(256) void k_scanA() {
    __shared__ int sm[256];
    int tx = threadIdx.x;
    int i = blockIdx.x * 256 + tx;
    int v = (i < NND) ? g_deg[i] - 1 : 0;
    sm[tx] = v;
    __syncthreads();
#pragma unroll
    for (int off = 1; off < 256; off <<= 1) {
        int p = (tx >= off) ? sm[tx - off] : 0;
        __syncthreads();
        sm[tx] += p;
        __syncthreads();
    }
    if (i < NND) g_rowtmp[i] = sm[tx] - v;
    if (tx == 255) g_bsum[blockIdx.x] = sm[255];
}
__global__ __launch_bounds__(256) void k_scanB(int nb) {
    __shared__ int sm[256];
    int tx = threadIdx.x;
    int v = (tx < nb) ? g_bsum[tx] : 0;
    sm[tx] = v;
    __syncthreads();
#pragma unroll
    for (int off = 1; off < 256; off <<= 1) {
        int p = (tx >= off) ? sm[tx - off] : 0;
        __syncthreads();
        sm[tx] += p;
        __syncthreads();
    }
    g_boff[tx] = sm[tx] - v;
}
__global__ void k_scanC() {
    int i = blockIdx.x * blockDim.x + threadIdx.x;
    if (i < NND) {
        int rp = g_rowtmp[i] + g_boff[i >> 8];
        g_rowptr[i] = rp;
        g_cursor[i] = rp;
    }
}
__global__ void k_fill(const int* __restrict__ row, const int* __restrict__ col, int E) {
    int e = blockIdx.x * blockDim.x + threadIdx.x;
    if (e >= E) return;
    int r = row[e];
    int pos = atomicAdd(&g_cursor[r], 1);
    g_csrcol[pos] = col[e];
}

// ---------------- weight preconvert: (fold) + tf32 + fragment permute ----------------
__device__ __forceinline__ uint32_t f2tf32(float f) {
    uint32_t u;
    asm("cvt.rna.tf32.f32 %0, %1;" : "=r"(u) : "f"(f));
    return u;
}
// B fragment (m16n8k8): lane l holds b_j = B[k = ki*8 + (l&3) + 4j][n = ni*8 + (l>>2)]
// layout: g_Bperm[(ki*16+ni)*64 + l*2 + j]  -> LDG.64 per lane per atom
__global__ void k_bperm(const float* __restrict__ W, int fold) {
    int t = blockIdx.x * blockDim.x + threadIdx.x;
    if (t >= HD * HD) return;
    int k = t >> 7, n = t & 127;
    float v = W[t];
    if (fold) v += W[t + HD * HD];
    int ki = k >> 3, ni = n >> 3, kk = k & 7, nn = n & 7;
    int l = (nn << 2) | (kk & 3);
    int j = kk >> 2;
    g_Bperm[(ki * 16 + ni) * 64 + l * 2 + j] = f2tf32(v);
}

// ---------------- TF32 tensor-core GEMM: C[M,128] = A[M,128] @ Bperm (+bias) --------
__device__ __forceinline__ void mma_tf32(float* d, const uint32_t* a, const uint32_t* b) {
    asm volatile(
        "mma.sync.aligned.m16n8k8.row.col.f32.tf32.tf32.f32 "
        "{%0,%1,%2,%3}, {%4,%5,%6,%7}, {%8,%9}, {%0,%1,%2,%3};"
        : "+f"(d[0]), "+f"(d[1]), "+f"(d[2]), "+f"(d[3])
        : "r"(a[0]), "r"(a[1]), "r"(a[2]), "r"(a[3]), "r"(b[0]), "r"(b[1]));
}
// A atom layout: Asp[(ki*8+mi)*128 + j*32 + lane]
//   element (row = mi*16+rr, kloc = ki*8+c):  lane = (rr&7)*4 + (c&3),
//   j = (rr>>3) | ((c>>2)<<1)   ->  staging float4(k-dir) = contiguous STS.128
__global__ __launch_bounds__(256) void k_gemm_tf32(const float* __restrict__ A,
                                                   const float* __restrict__ bias,
                                                   float* __restrict__ C, int M) {
    __shared__ uint32_t Asp[32 * 128];
    int tid = threadIdx.x;
    int lane = tid & 31;
    int w = tid >> 5;
    int wm = w >> 2, wn = w & 3;          // 2(m) x 4(n) warps
    int gRow0 = blockIdx.x * 128;
    float acc[4][4][4];
#pragma unroll
    for (int i = 0; i < 4; i++)
#pragma unroll
        for (int t = 0; t < 4; t++)
#pragma unroll
            for (int u = 0; u < 4; u++) acc[i][t][u] = 0.f;

    // staging coords (fixed per thread, 4 float4 units each)
    for (int kk = 0; kk < 128; kk += 32) {
#pragma unroll
        for (int q = 0; q < 4; q++) {
            int fid = tid + q * 256;          // 0..1023
            int row = fid >> 3;               // 0..127
            int c4  = fid & 7;                // float4 index in 32-k chunk
            int gr  = gRow0 + row;
            float4 v = make_float4(0.f, 0.f, 0.f, 0.f);
            if (gr < M) v = *(const float4*)(A + (size_t)gr * 128 + kk + c4 * 4);
            int mi = row >> 4, rr = row & 15;
            int ki = c4 >> 1;
            int j  = (rr >> 3) | ((c4 & 1) << 1);
            uint4 o;
            o.x = f2tf32(v.x); o.y = f2tf32(v.y); o.z = f2tf32(v.z); o.w = f2tf32(v.w);
            *(uint4*)(&Asp[(ki * 8 + mi) * 128 + j * 32 + (rr & 7) * 4]) = o;
        }
        __syncthreads();
#pragma unroll
        for (int ki = 0; ki < 4; ki++) {
            uint32_t af[4][4];
#pragma unroll
            for (int i = 0; i < 4; i++) {
                const uint32_t* base = &Asp[(ki * 8 + wm * 4 + i) * 128];
                af[i][0] = base[lane];
                af[i][1] = base[32 + lane];
                af[i][2] = base[64 + lane];
                af[i][3] = base[96 + lane];
            }
            uint32_t bf[4][2];
            int kig = (kk >> 3) + ki;
#pragma unroll
            for (int t = 0; t < 4; t++) {
                uint2 b2 = *(const uint2*)(&g_Bperm[(kig * 16 + wn * 4 + t) * 64 + lane * 2]);
                bf[t][0] = b2.x; bf[t][1] = b2.y;
            }
#pragma unroll
            for (int i = 0; i < 4; i++)
#pragma unroll
                for (int t = 0; t < 4; t++) mma_tf32(acc[i][t], af[i], bf[t]);
        }
        __syncthreads();
    }
    int g = lane >> 2, t4 = lane & 3;
#pragma unroll
    for (int i = 0; i < 4; i++) {
#pragma unroll
        for (int t = 0; t < 4; t++) {
            int col = (wn * 4 + t) * 8 + 2 * t4;
            float b0 = bias ? bias[col] : 0.f;
            float b1 = bias ? bias[col + 1] : 0.f;
            int row0 = gRow0 + (wm * 4 + i) * 16 + g;
            int row1 = row0 + 8;
            if (row0 < M)
                *(float2*)(C + (size_t)row0 * 128 + col) =
                    make_float2(acc[i][t][0] + b0, acc[i][t][1] + b1);
            if (row1 < M)
                *(float2*)(C + (size_t)row1 * 128 + col) =
                    make_float2(acc[i][t][2] + b0, acc[i][t][3] + b1);
        }
    }
}

// ---------------- fused GCN (warp per node, CSR) ----------------
__global__ __launch_bounds__(256) void k_gcn(const float* __restrict__ bias) {
    int r = (blockIdx.x * blockDim.x + threadIdx.x) >> 5;
    int lane = threadIdx.x & 31;
    if (r >= NND) return;
    int beg = g_rowptr[r];
    int cnt = g_deg[r] - 1;
    float dr = g_dinv[r];
    const float* xw = g_bufXW;
    float4 acc = *(const float4*)(xw + (size_t)r * HD + lane * 4);
    float dr2 = dr * dr;
    acc.x *= dr2; acc.y *= dr2; acc.z *= dr2; acc.w *= dr2;
    for (int j = 0; j < cnt; j++) {
        int c = g_csrcol[beg + j];
        float nrm = dr * g_dinv[c];
        float4 v = *(const float4*)(xw + (size_t)c * HD + lane * 4);
        acc.x += v.x * nrm; acc.y += v.y * nrm;
        acc.z += v.z * nrm; acc.w += v.w * nrm;
    }
    float4 b = *(const float4*)(bias + lane * 4);
    acc.x = fmaxf(acc.x + b.x, 0.f);
    acc.y = fmaxf(acc.y + b.y, 0.f);
    acc.z = fmaxf(acc.z + b.z, 0.f);
    acc.w = fmaxf(acc.w + b.w, 0.f);
    *(float4*)(g_bufACC + (size_t)r * HD + lane * 4) = acc;
}

// ---------------- fused GAT: single-pass online softmax (warp per node) ----------------
__device__ __forceinline__ float warp_sum(float s) {
#pragma unroll
    for (int o = 16; o; o >>= 1) s += __shfl_xor_sync(0xffffffffu, s, o);
    return s;
}
__global__ __launch_bounds__(256) void k_gat() {
    int r = (blockIdx.x * blockDim.x + threadIdx.x) >> 5;
    int lane = threadIdx.x & 31;
    if (r >= NND) return;
    int beg = g_rowptr[r];
    int cnt = g_deg[r] - 1;
    const float* hh = g_bufHH;
    float4 hr = *(const float4*)(hh + (size_t)r * HD + lane * 4);
    // init with appended self loop: alpha_self = |h_r|^2 (>=0, leaky no-op)
    float m = warp_sum(hr.x * hr.x + hr.y * hr.y + hr.z * hr.z + hr.w * hr.w);
    float denom = 1.f;
    float4 acc = hr;
    for (int j = 0; j < cnt; j++) {
        int c = g_csrcol[beg + j];
        if (c == r) continue;                    // masked original self loop
        float4 hc = *(const float4*)(hh + (size_t)c * HD + lane * 4);
        float d = warp_sum(hr.x * hc.x + hr.y * hc.y + hr.z * hc.z + hr.w * hc.w);
        float al = (d > 0.f) ? d : 0.2f * d;
        // online softmax update (all values warp-uniform -> no divergence)
        float mn = fmaxf(m, al);
        float sOld = __expf(m - mn);
        float eNew = __expf(al - mn);
        denom = denom * sOld + eNew;
        acc.x = acc.x * sOld + eNew * hc.x;
        acc.y = acc.y * sOld + eNew * hc.y;
        acc.z = acc.z * sOld + eNew * hc.z;
        acc.w = acc.w * sOld + eNew * hc.w;
        m = mn;
    }
    float inv = 1.f / fmaxf(denom, 1e-16f);
    acc.x *= inv; acc.y *= inv; acc.z *= inv; acc.w *= inv;
    *(float4*)(g_bufOUT + (size_t)r * HD + lane * 4) = acc;
}

// ---------------- final mean pool ----------------
__global__ void k_zero_out(float* out) {
    int t = threadIdx.x;
    if (t < 2 * HD) out[t] = 0.f;
}
__global__ void k_mean(float* __restrict__ out) {
    int col = threadIdx.x;                    // 128 threads
    float s = 0.f;
    for (int i = blockIdx.x; i < NND; i += gridDim.x)
        s += g_bufOUT[(size_t)i * HD + col];
    s *= (1.0f / NND);
    atomicAdd(&out[col], s);
    atomicAdd(&out[col + HD], s);
}

// ---------------- launch ----------------
extern "C" void kernel_launch(void* const* d_in, const int* in_sizes, int n_in,
                              void* d_out, int out_size) {
    const float* x   = (const float*)d_in[0];
    const int*   ei  = (const int*)d_in[1];     // int32 (JAX x64 disabled)
    int E = in_sizes[1] / 2;
    const int* row = ei;
    const int* col = ei + E;
    const float* Wg[3] = {(const float*)d_in[2], (const float*)d_in[6],  (const float*)d_in[10]};
    const float* bg[3] = {(const float*)d_in[3], (const float*)d_in[7],  (const float*)d_in[11]};
    const float* Wa[3] = {(const float*)d_in[4], (const float*)d_in[8],  (const float*)d_in[12]};
    const float* ba[3] = {(const float*)d_in[5], (const float*)d_in[9],  (const float*)d_in[13]};
    float* out = (float*)d_out;

    float *pXW, *pACC, *pHH, *pOUT;
    cudaGetSymbolAddress((void**)&pXW,  g_bufXW);
    cudaGetSymbolAddress((void**)&pACC, g_bufACC);
    cudaGetSymbolAddress((void**)&pHH,  g_bufHH);
    cudaGetSymbolAddress((void**)&pOUT, g_bufOUT);

    const int TB = 256;
    int gN  = (NND + TB - 1) / TB;              // 157
    int gE  = (E + TB - 1) / TB;
    int gNw = (NND + 7) / 8;
    int gGemm = (NND + 127) / 128;              // 313

    k_deg_init<<<gN, TB>>>();
    k_deg_count<<<gE, TB>>>(row, E);
    k_dinv<<<gN, TB>>>();
    k_scanA<<<gN, TB>>>();
    k_scanB<<<1, TB>>>(gN);
    k_scanC<<<gN, TB>>>();
    k_fill<<<gE, TB>>>(row, col, E);

    const float* cur = x;
    for (int l = 0; l < 3; l++) {
        k_bperm<<<64, TB>>>(Wg[l], l > 0 ? 1 : 0);
        k_gemm_tf32<<<gGemm, TB>>>(cur, nullptr, pXW, NND);
        k_gcn<<<gNw, TB>>>(bg[l]);
        k_bperm<<<64, TB>>>(Wa[l], 0);
        k_gemm_tf32<<<gGemm, TB>>>(pACC, ba[l], pHH, NND);
        k_gat<<<gNw, TB>>>();
        cur = pOUT;
    }
    k_zero_out<<<1, TB>>>(out);
    k_mean<<<512, HD>>>(out);
}

// round 7
// speedup vs baseline: 2.8886x; 1.1154x over previous
#include <cuda_runtime.h>
#include <cstdint>
#include <math_constants.h>

#define NND 40000
#define HD  128
#define EED 640000

// ---------------- scratch (device globals: allocation-free) ----------------
__device__ float    g_bufXW [(size_t)NND * HD];
__device__ float    g_bufACC[(size_t)NND * HD];
__device__ float    g_bufHH [(size_t)NND * HD];
__device__ float    g_bufOUT[(size_t)NND * HD];
__device__ int      g_deg   [NND];
__device__ float    g_dinv  [NND];
__device__ int      g_rowptr[NND];
__device__ int      g_cursor[NND];
__device__ int      g_rowtmp[NND];
__device__ int      g_bsum  [256];
__device__ int      g_boff  [256];
__device__ int      g_csrcol[EED];
__device__ uint32_t g_Bperm [HD * HD];   // tf32 fragment-permuted weight (per layer)

// ---------------- degree / norm ----------------
__global__ void k_deg_init() {
    int i = blockIdx.x * blockDim.x + threadIdx.x;
    if (i < NND) g_deg[i] = 1;
}
__global__ void k_deg_count(const int* __restrict__ row, int E) {
    int e = blockIdx.x * blockDim.x + threadIdx.x;
    if (e < E) atomicAdd(&g_deg[row[e]], 1);
}
__global__ void k_dinv() {
    int i = blockIdx.x * blockDim.x + threadIdx.x;
    if (i < NND) g_dinv[i] = rsqrtf((float)g_deg[i]);
}

// ---------------- hierarchical exclusive scan of (deg-1) ----------------
__global__ __launch_bounds__(256) void k_scanA() {
    __shared__ int sm[256];
    int tx = threadIdx.x;
    int i = blockIdx.x * 256 + tx;
    int v = (i < NND) ? g_deg[i] - 1 : 0;
    sm[tx] = v;
    __syncthreads();
#pragma unroll
    for (int off = 1; off < 256; off <<= 1) {
        int p = (tx >= off) ? sm[tx - off] : 0;
        __syncthreads();
        sm[tx] += p;
        __syncthreads();
    }
    if (i < NND) g_rowtmp[i] = sm[tx] - v;
    if (tx == 255) g_bsum[blockIdx.x] = sm[255];
}
__global__ __launch_bounds__(256) void k_scanB(int nb) {
    __shared__ int sm[256];
    int tx = threadIdx.x;
    int v = (tx < nb) ? g_bsum[tx] : 0;
    sm[tx] = v;
    __syncthreads();
#pragma unroll
    for (int off = 1; off < 256; off <<= 1) {
        int p = (tx >= off) ? sm[tx - off] : 0;
        __syncthreads();
        sm[tx] += p;
        __syncthreads();
    }
    g_boff[tx] = sm[tx] - v;
}
__global__ void k_scanC() {
    int i = blockIdx.x * blockDim.x + threadIdx.x;
    if (i < NND) {
        int rp = g_rowtmp[i] + g_boff[i >> 8];
        g_rowptr[i] = rp;
        g_cursor[i] = rp;
    }
}
__global__ void k_fill(const int* __restrict__ row, const int* __restrict__ col, int E) {
    int e = blockIdx.x * blockDim.x + threadIdx.x;
    if (e >= E) return;
    int r = row[e];
    int pos = atomicAdd(&g_cursor[r], 1);
    g_csrcol[pos] = col[e];
}

// ---------------- weight preconvert: (fold) + tf32 + fragment permute ----------------
__device__ __forceinline__ uint32_t f2tf32(float f) {
    uint32_t u;
    asm("cvt.rna.tf32.f32 %0, %1;" : "=r"(u) : "f"(f));
    return u;
}
__global__ void k_bperm(const float* __restrict__ W, int fold) {
    int t = blockIdx.x * blockDim.x + threadIdx.x;
    if (t >= HD * HD) return;
    int k = t >> 7, n = t & 127;
    float v = W[t];
    if (fold) v += W[t + HD * HD];
    int ki = k >> 3, ni = n >> 3, kk = k & 7, nn = n & 7;
    int l = (nn << 2) | (kk & 3);
    int j = kk >> 2;
    g_Bperm[(ki * 16 + ni) * 64 + l * 2 + j] = f2tf32(v);
}

// ---------------- TF32 tensor-core GEMM: C[M,128] = A[M,128] @ Bperm ---------------
// epilogue: C = (acc + bias) * rowscale[row]   (bias/rowscale optional)
__device__ __forceinline__ void mma_tf32(float* d, const uint32_t* a, const uint32_t* b) {
    asm volatile(
        "mma.sync.aligned.m16n8k8.row.col.f32.tf32.tf32.f32 "
        "{%0,%1,%2,%3}, {%4,%5,%6,%7}, {%8,%9}, {%0,%1,%2,%3};"
        : "+f"(d[0]), "+f"(d[1]), "+f"(d[2]), "+f"(d[3])
        : "r"(a[0]), "r"(a[1]), "r"(a[2]), "r"(a[3]), "r"(b[0]), "r"(b[1]));
}
__global__ __launch_bounds__(256) void k_gemm_tf32(const float* __restrict__ A,
                                                   const float* __restrict__ bias,
                                                   const float* __restrict__ rowscale,
                                                   float* __restrict__ C, int M) {
    __shared__ uint32_t Asp[32 * 128];
    int tid = threadIdx.x;
    int lane = tid & 31;
    int w = tid >> 5;
    int wm = w >> 2, wn = w & 3;
    int gRow0 = blockIdx.x * 128;
    float acc[4][4][4];
#pragma unroll
    for (int i = 0; i < 4; i++)
#pragma unroll
        for (int t = 0; t < 4; t++)
#pragma unroll
            for (int u = 0; u < 4; u++) acc[i][t][u] = 0.f;

    for (int kk = 0; kk < 128; kk += 32) {
#pragma unroll
        for (int q = 0; q < 4; q++) {
            int fid = tid + q * 256;
            int row = fid >> 3;
            int c4  = fid & 7;
            int gr  = gRow0 + row;
            float4 v = make_float4(0.f, 0.f, 0.f, 0.f);
            if (gr < M) v = *(const float4*)(A + (size_t)gr * 128 + kk + c4 * 4);
            int mi = row >> 4, rr = row & 15;
            int ki = c4 >> 1;
            int j  = (rr >> 3) | ((c4 & 1) << 1);
            uint4 o;
            o.x = f2tf32(v.x); o.y = f2tf32(v.y); o.z = f2tf32(v.z); o.w = f2tf32(v.w);
            *(uint4*)(&Asp[(ki * 8 + mi) * 128 + j * 32 + (rr & 7) * 4]) = o;
        }
        __syncthreads();
#pragma unroll
        for (int ki = 0; ki < 4; ki++) {
            uint32_t af[4][4];
#pragma unroll
            for (int i = 0; i < 4; i++) {
                const uint32_t* base = &Asp[(ki * 8 + wm * 4 + i) * 128];
                af[i][0] = base[lane];
                af[i][1] = base[32 + lane];
                af[i][2] = base[64 + lane];
                af[i][3] = base[96 + lane];
            }
            uint32_t bf[4][2];
            int kig = (kk >> 3) + ki;
#pragma unroll
            for (int t = 0; t < 4; t++) {
                uint2 b2 = *(const uint2*)(&g_Bperm[(kig * 16 + wn * 4 + t) * 64 + lane * 2]);
                bf[t][0] = b2.x; bf[t][1] = b2.y;
            }
#pragma unroll
            for (int i = 0; i < 4; i++)
#pragma unroll
                for (int t = 0; t < 4; t++) mma_tf32(acc[i][t], af[i], bf[t]);
        }
        __syncthreads();
    }
    int g = lane >> 2, t4 = lane & 3;
#pragma unroll
    for (int i = 0; i < 4; i++) {
        int row0 = gRow0 + (wm * 4 + i) * 16 + g;
        int row1 = row0 + 8;
        float rs0 = 1.f, rs1 = 1.f;
        if (rowscale) {
            if (row0 < M) rs0 = rowscale[row0];
            if (row1 < M) rs1 = rowscale[row1];
        }
#pragma unroll
        for (int t = 0; t < 4; t++) {
            int col = (wn * 4 + t) * 8 + 2 * t4;
            float b0 = bias ? bias[col] : 0.f;
            float b1 = bias ? bias[col + 1] : 0.f;
            if (row0 < M)
                *(float2*)(C + (size_t)row0 * 128 + col) =
                    make_float2((acc[i][t][0] + b0) * rs0, (acc[i][t][1] + b1) * rs0);
            if (row1 < M)
                *(float2*)(C + (size_t)row1 * 128 + col) =
                    make_float2((acc[i][t][2] + b0) * rs1, (acc[i][t][3] + b1) * rs1);
        }
    }
}

// ---------------- fused GCN (warp per node, CSR, xw pre-scaled by dinv) -------------
// xwS = xw * dinv.  out = (xwS[r] + sum_c xwS[c]) * dr + bias, relu
//   self: xw_r*dr*dr ✓   neighbor: xw_c*dc*dr ✓
__global__ __launch_bounds__(256) void k_gcn(const float* __restrict__ bias) {
    int r = (blockIdx.x * blockDim.x + threadIdx.x) >> 5;
    int lane = threadIdx.x & 31;
    if (r >= NND) return;
    int beg = g_rowptr[r];
    int cnt = g_deg[r] - 1;
    float dr = g_dinv[r];
    const float* xw = g_bufXW;
    float4 acc = *(const float4*)(xw + (size_t)r * HD + lane * 4);  // xwS[r] (no extra dr!)
    int j = 0;
    for (; j + 4 <= cnt; j += 4) {
        int c0 = g_csrcol[beg + j];
        int c1 = g_csrcol[beg + j + 1];
        int c2 = g_csrcol[beg + j + 2];
        int c3 = g_csrcol[beg + j + 3];
        float4 v0 = *(const float4*)(xw + (size_t)c0 * HD + lane * 4);
        float4 v1 = *(const float4*)(xw + (size_t)c1 * HD + lane * 4);
        float4 v2 = *(const float4*)(xw + (size_t)c2 * HD + lane * 4);
        float4 v3 = *(const float4*)(xw + (size_t)c3 * HD + lane * 4);
        acc.x += (v0.x + v1.x) + (v2.x + v3.x);
        acc.y += (v0.y + v1.y) + (v2.y + v3.y);
        acc.z += (v0.z + v1.z) + (v2.z + v3.z);
        acc.w += (v0.w + v1.w) + (v2.w + v3.w);
    }
    for (; j < cnt; j++) {
        int c = g_csrcol[beg + j];
        float4 v = *(const float4*)(xw + (size_t)c * HD + lane * 4);
        acc.x += v.x; acc.y += v.y; acc.z += v.z; acc.w += v.w;
    }
    float4 b = *(const float4*)(bias + lane * 4);
    acc.x = fmaxf(acc.x * dr + b.x, 0.f);
    acc.y = fmaxf(acc.y * dr + b.y, 0.f);
    acc.z = fmaxf(acc.z * dr + b.z, 0.f);
    acc.w = fmaxf(acc.w * dr + b.w, 0.f);
    *(float4*)(g_bufACC + (size_t)r * HD + lane * 4) = acc;
}

// ---------------- fused GAT: blocked single-pass online softmax ----------------------
__device__ __forceinline__ float warp_sum(float s) {
#pragma unroll
    for (int o = 16; o; o >>= 1) s += __shfl_xor_sync(0xffffffffu, s, o);
    return s;
}
__global__ __launch_bounds__(256) void k_gat() {
    int r = (blockIdx.x * blockDim.x + threadIdx.x) >> 5;
    int lane = threadIdx.x & 31;
    if (r >= NND) return;
    int beg = g_rowptr[r];
    int cnt = g_deg[r] - 1;
    const float* hh = g_bufHH;
    float4 hr = *(const float4*)(hh + (size_t)r * HD + lane * 4);
    float m = warp_sum(hr.x * hr.x + hr.y * hr.y + hr.z * hr.z + hr.w * hr.w);
    float denom = 1.f;
    float4 acc = hr;
    int j = 0;
    for (; j + 4 <= cnt; j += 4) {
        int c0 = g_csrcol[beg + j];
        int c1 = g_csrcol[beg + j + 1];
        int c2 = g_csrcol[beg + j + 2];
        int c3 = g_csrcol[beg + j + 3];
        float4 h0 = *(const float4*)(hh + (size_t)c0 * HD + lane * 4);
        float4 h1 = *(const float4*)(hh + (size_t)c1 * HD + lane * 4);
        float4 h2 = *(const float4*)(hh + (size_t)c2 * HD + lane * 4);
        float4 h3 = *(const float4*)(hh + (size_t)c3 * HD + lane * 4);
        float d0 = hr.x * h0.x + hr.y * h0.y + hr.z * h0.z + hr.w * h0.w;
        float d1 = hr.x * h1.x + hr.y * h1.y + hr.z * h1.z + hr.w * h1.w;
        float d2 = hr.x * h2.x + hr.y * h2.y + hr.z * h2.z + hr.w * h2.w;
        float d3 = hr.x * h3.x + hr.y * h3.y + hr.z * h3.z + hr.w * h3.w;
#pragma unroll
        for (int o = 16; o; o >>= 1) {
            d0 += __shfl_xor_sync(0xffffffffu, d0, o);
            d1 += __shfl_xor_sync(0xffffffffu, d1, o);
            d2 += __shfl_xor_sync(0xffffffffu, d2, o);
            d3 += __shfl_xor_sync(0xffffffffu, d3, o);
        }
        float a0 = (c0 == r) ? -CUDART_INF_F : ((d0 > 0.f) ? d0 : 0.2f * d0);
        float a1 = (c1 == r) ? -CUDART_INF_F : ((d1 > 0.f) ? d1 : 0.2f * d1);
        float a2 = (c2 == r) ? -CUDART_INF_F : ((d2 > 0.f) ? d2 : 0.2f * d2);
        float a3 = (c3 == r) ? -CUDART_INF_F : ((d3 > 0.f) ? d3 : 0.2f * d3);
        float mblk = fmaxf(fmaxf(a0, a1), fmaxf(a2, a3));
        float mn = fmaxf(m, mblk);
        float sOld = __expf(m - mn);
        float e0 = __expf(a0 - mn);
        float e1 = __expf(a1 - mn);
        float e2 = __expf(a2 - mn);
        float e3 = __expf(a3 - mn);
        denom = denom * sOld + ((e0 + e1) + (e2 + e3));
        acc.x = acc.x * sOld + e0 * h0.x + e1 * h1.x + e2 * h2.x + e3 * h3.x;
        acc.y = acc.y * sOld + e0 * h0.y + e1 * h1.y + e2 * h2.y + e3 * h3.y;
        acc.z = acc.z * sOld + e0 * h0.z + e1 * h1.z + e2 * h2.z + e3 * h3.z;
        acc.w = acc.w * sOld + e0 * h0.w + e1 * h1.w + e2 * h2.w + e3 * h3.w;
        m = mn;
    }
    for (; j < cnt; j++) {
        int c = g_csrcol[beg + j];
        if (c == r) continue;
        float4 hc = *(const float4*)(hh + (size_t)c * HD + lane * 4);
        float d = warp_sum(hr.x * hc.x + hr.y * hc.y + hr.z * hc.z + hr.w * hc.w);
        float al = (d > 0.f) ? d : 0.2f * d;
        float mn = fmaxf(m, al);
        float sOld = __expf(m - mn);
        float eNew = __expf(al - mn);
        denom = denom * sOld + eNew;
        acc.x = acc.x * sOld + eNew * hc.x;
        acc.y = acc.y * sOld + eNew * hc.y;
        acc.z = acc.z * sOld + eNew * hc.z;
        acc.w = acc.w * sOld + eNew * hc.w;
        m = mn;
    }
    float inv = 1.f / fmaxf(denom, 1e-16f);
    acc.x *= inv; acc.y *= inv; acc.z *= inv; acc.w *= inv;
    *(float4*)(g_bufOUT + (size_t)r * HD + lane * 4) = acc;
}

// ---------------- final mean pool ----------------
__global__ void k_zero_out(float* out) {
    int t = threadIdx.x;
    if (t < 2 * HD) out[t] = 0.f;
}
__global__ void k_mean(float* __restrict__ out) {
    int col = threadIdx.x;                    // 128 threads
    float s = 0.f;
    for (int i = blockIdx.x; i < NND; i += gridDim.x)
        s += g_bufOUT[(size_t)i * HD + col];
    s *= (1.0f / NND);
    atomicAdd(&out[col], s);
    atomicAdd(&out[col + HD], s);
}

// ---------------- launch ----------------
extern "C" void kernel_launch(void* const* d_in, const int* in_sizes, int n_in,
                              void* d_out, int out_size) {
    const float* x   = (const float*)d_in[0];
    const int*   ei  = (const int*)d_in[1];     // int32 (JAX x64 disabled)
    int E = in_sizes[1] / 2;
    const int* row = ei;
    const int* col = ei + E;
    const float* Wg[3] = {(const float*)d_in[2], (const float*)d_in[6],  (const float*)d_in[10]};
    const float* bg[3] = {(const float*)d_in[3], (const float*)d_in[7],  (const float*)d_in[11]};
    const float* Wa[3] = {(const float*)d_in[4], (const float*)d_in[8],  (const float*)d_in[12]};
    const float* ba[3] = {(const float*)d_in[5], (const float*)d_in[9],  (const float*)d_in[13]};
    float* out = (float*)d_out;

    float *pXW, *pACC, *pHH, *pOUT, *pDinv;
    cudaGetSymbolAddress((void**)&pXW,  g_bufXW);
    cudaGetSymbolAddress((void**)&pACC, g_bufACC);
    cudaGetSymbolAddress((void**)&pHH,  g_bufHH);
    cudaGetSymbolAddress((void**)&pOUT, g_bufOUT);
    cudaGetSymbolAddress((void**)&pDinv, g_dinv);

    const int TB = 256;
    int gN  = (NND + TB - 1) / TB;              // 157
    int gE  = (E + TB - 1) / TB;
    int gNw = (NND + 7) / 8;
    int gGemm = (NND + 127) / 128;              // 313

    k_deg_init<<<gN, TB>>>();
    k_deg_count<<<gE, TB>>>(row, E);
    k_dinv<<<gN, TB>>>();
    k_scanA<<<gN, TB>>>();
    k_scanB<<<1, TB>>>(gN);
    k_scanC<<<gN, TB>>>();
    k_fill<<<gE, TB>>>(row, col, E);

    const float* cur = x;
    for (int l = 0; l < 3; l++) {
        k_bperm<<<64, TB>>>(Wg[l], l > 0 ? 1 : 0);
        k_gemm_tf32<<<gGemm, TB>>>(cur, nullptr, pDinv, pXW, NND);   // xwS = xw * dinv
        k_gcn<<<gNw, TB>>>(bg[l]);
        k_bperm<<<64, TB>>>(Wa[l], 0);
        k_gemm_tf32<<<gGemm, TB>>>(pACC, ba[l], nullptr, pHH, NND);
        k_gat<<<gNw, TB>>>();
        cur = pOUT;
    }
    k_zero_out<<<1, TB>>>(out);
    k_mean<<<512, HD>>>(out);
}

// round 8
// speedup vs baseline: 3.1319x; 1.0842x over previous
#include <cuda_runtime.h>
#include <cuda_fp16.h>
#include <cstdint>
#include <math_constants.h>

#define NND 40000
#define HD  128
#define EED 640000

// ---------------- scratch (device globals: allocation-free) ----------------
__device__ __half   g_bufXW [(size_t)NND * HD];   // GCN GEMM out, fp16 (gathered)
__device__ __half   g_bufHH [(size_t)NND * HD];   // GAT GEMM out, fp16 (gathered)
__device__ float    g_bufACC[(size_t)NND * HD];   // relu(GCN) out, fp32 (GEMM input)
__device__ float    g_bufOUT[(size_t)NND * HD];   // GAT out, fp32 (GEMM input / pool)
__device__ int      g_deg   [NND];
__device__ float    g_dinv  [NND];
__device__ int      g_rowptr[NND];
__device__ int      g_cursor[NND];
__device__ int      g_rowtmp[NND];
__device__ int      g_bsum  [256];
__device__ int      g_boff  [256];
__device__ int      g_csrcol[EED];
__device__ uint32_t g_Bperm [HD * HD];

// ---------------- helpers ----------------
__device__ __forceinline__ float4 h8_to_f4(uint2 u) {
    __half2 a = *(__half2*)&u.x, b = *(__half2*)&u.y;
    float2 fa = __half22float2(a), fb = __half22float2(b);
    return make_float4(fa.x, fa.y, fb.x, fb.y);
}

// ---------------- degree / norm ----------------
__global__ void k_deg_init() {
    int i = blockIdx.x * blockDim.x + threadIdx.x;
    if (i < NND) g_deg[i] = 1;
}
__global__ void k_deg_count(const int* __restrict__ row, int E) {
    int e = blockIdx.x * blockDim.x + threadIdx.x;
    if (e < E) atomicAdd(&g_deg[row[e]], 1);
}

// ---------------- hierarchical exclusive scan of (deg-1), + dinv ----------------
__global__ __launch_bounds__(256) void k_scanA() {
    __shared__ int sm[256];
    int tx = threadIdx.x;
    int i = blockIdx.x * 256 + tx;
    int d = (i < NND) ? g_deg[i] : 1;
    if (i < NND) g_dinv[i] = rsqrtf((float)d);
    int v = d - 1;
    if (i >= NND) v = 0;
    sm[tx] = v;
    __syncthreads();
#pragma unroll
    for (int off = 1; off < 256; off <<= 1) {
        int p = (tx >= off) ? sm[tx - off] : 0;
        __syncthreads();
        sm[tx] += p;
        __syncthreads();
    }
    if (i < NND) g_rowtmp[i] = sm[tx] - v;
    if (tx == 255) g_bsum[blockIdx.x] = sm[255];
}
__global__ __launch_bounds__(256) void k_scanB(int nb) {
    __shared__ int sm[256];
    int tx = threadIdx.x;
    int v = (tx < nb) ? g_bsum[tx] : 0;
    sm[tx] = v;
    __syncthreads();
#pragma unroll
    for (int off = 1; off < 256; off <<= 1) {
        int p = (tx >= off) ? sm[tx - off] : 0;
        __syncthreads();
        sm[tx] += p;
        __syncthreads();
    }
    g_boff[tx] = sm[tx] - v;
}
__global__ void k_scanC() {
    int i = blockIdx.x * blockDim.x + threadIdx.x;
    if (i < NND) {
        int rp = g_rowtmp[i] + g_boff[i >> 8];
        g_rowptr[i] = rp;
        g_cursor[i] = rp;
    }
}
__global__ void k_fill(const int* __restrict__ row, const int* __restrict__ col, int E) {
    int e = blockIdx.x * blockDim.x + threadIdx.x;
    if (e >= E) return;
    int r = row[e];
    int pos = atomicAdd(&g_cursor[r], 1);
    g_csrcol[pos] = col[e];
}

// ---------------- weight preconvert: (fold) + tf32 + fragment permute ----------------
__device__ __forceinline__ uint32_t f2tf32(float f) {
    uint32_t u;
    asm("cvt.rna.tf32.f32 %0, %1;" : "=r"(u) : "f"(f));
    return u;
}
__global__ void k_bperm(const float* __restrict__ W, int fold) {
    int t = blockIdx.x * blockDim.x + threadIdx.x;
    if (t >= HD * HD) return;
    int k = t >> 7, n = t & 127;
    float v = W[t];
    if (fold) v += W[t + HD * HD];
    int ki = k >> 3, ni = n >> 3, kk = k & 7, nn = n & 7;
    int l = (nn << 2) | (kk & 3);
    int j = kk >> 2;
    g_Bperm[(ki * 16 + ni) * 64 + l * 2 + j] = f2tf32(v);
}

// ---------------- TF32 tensor-core GEMM: Ch[M,128] = A[M,128] @ Bperm (fp16 out) ----
// epilogue: Ch = half((acc + bias) * rowscale[row])
__device__ __forceinline__ void mma_tf32(float* d, const uint32_t* a, const uint32_t* b) {
    asm volatile(
        "mma.sync.aligned.m16n8k8.row.col.f32.tf32.tf32.f32 "
        "{%0,%1,%2,%3}, {%4,%5,%6,%7}, {%8,%9}, {%0,%1,%2,%3};"
        : "+f"(d[0]), "+f"(d[1]), "+f"(d[2]), "+f"(d[3])
        : "r"(a[0]), "r"(a[1]), "r"(a[2]), "r"(a[3]), "r"(b[0]), "r"(b[1]));
}
__global__ __launch_bounds__(256) void k_gemm_tf32(const float* __restrict__ A,
                                                   const float* __restrict__ bias,
                                                   const float* __restrict__ rowscale,
                                                   __half* __restrict__ Ch, int M) {
    __shared__ uint32_t Asp[32 * 128];
    int tid = threadIdx.x;
    int lane = tid & 31;
    int w = tid >> 5;
    int wm = w >> 2, wn = w & 3;
    int gRow0 = blockIdx.x * 128;
    float acc[4][4][4];
#pragma unroll
    for (int i = 0; i < 4; i++)
#pragma unroll
        for (int t = 0; t < 4; t++)
#pragma unroll
            for (int u = 0; u < 4; u++) acc[i][t][u] = 0.f;

    for (int kk = 0; kk < 128; kk += 32) {
#pragma unroll
        for (int q = 0; q < 4; q++) {
            int fid = tid + q * 256;
            int row = fid >> 3;
            int c4  = fid & 7;
            int gr  = gRow0 + row;
            float4 v = make_float4(0.f, 0.f, 0.f, 0.f);
            if (gr < M) v = *(const float4*)(A + (size_t)gr * 128 + kk + c4 * 4);
            int mi = row >> 4, rr = row & 15;
            int ki = c4 >> 1;
            int j  = (rr >> 3) | ((c4 & 1) << 1);
            uint4 o;
            o.x = f2tf32(v.x); o.y = f2tf32(v.y); o.z = f2tf32(v.z); o.w = f2tf32(v.w);
            *(uint4*)(&Asp[(ki * 8 + mi) * 128 + j * 32 + (rr & 7) * 4]) = o;
        }
        __syncthreads();
#pragma unroll
        for (int ki = 0; ki < 4; ki++) {
            uint32_t af[4][4];
#pragma unroll
            for (int i = 0; i < 4; i++) {
                const uint32_t* base = &Asp[(ki * 8 + wm * 4 + i) * 128];
                af[i][0] = base[lane];
                af[i][1] = base[32 + lane];
                af[i][2] = base[64 + lane];
                af[i][3] = base[96 + lane];
            }
            uint32_t bf[4][2];
            int kig = (kk >> 3) + ki;
#pragma unroll
            for (int t = 0; t < 4; t++) {
                uint2 b2 = *(const uint2*)(&g_Bperm[(kig * 16 + wn * 4 + t) * 64 + lane * 2]);
                bf[t][0] = b2.x; bf[t][1] = b2.y;
            }
#pragma unroll
            for (int i = 0; i < 4; i++)
#pragma unroll
                for (int t = 0; t < 4; t++) mma_tf32(acc[i][t], af[i], bf[t]);
        }
        __syncthreads();
    }
    int g = lane >> 2, t4 = lane & 3;
#pragma unroll
    for (int i = 0; i < 4; i++) {
        int row0 = gRow0 + (wm * 4 + i) * 16 + g;
        int row1 = row0 + 8;
        float rs0 = 1.f, rs1 = 1.f;
        if (rowscale) {
            if (row0 < M) rs0 = rowscale[row0];
            if (row1 < M) rs1 = rowscale[row1];
        }
#pragma unroll
        for (int t = 0; t < 4; t++) {
            int col = (wn * 4 + t) * 8 + 2 * t4;
            float b0 = bias ? bias[col] : 0.f;
            float b1 = bias ? bias[col + 1] : 0.f;
            if (row0 < M)
                *(__half2*)(Ch + (size_t)row0 * 128 + col) =
                    __floats2half2_rn((acc[i][t][0] + b0) * rs0, (acc[i][t][1] + b1) * rs0);
            if (row1 < M)
                *(__half2*)(Ch + (size_t)row1 * 128 + col) =
                    __floats2half2_rn((acc[i][t][2] + b0) * rs1, (acc[i][t][3] + b1) * rs1);
        }
    }
}

// ---------------- fused GCN (warp per node, CSR, fp16 gathered, fp32 accum) ---------
// xwS = half(xw * dinv).  out = (xwS[r] + sum_c xwS[c]) * dr + bias, relu
__global__ __launch_bounds__(256) void k_gcn(const float* __restrict__ bias) {
    int r = (blockIdx.x * blockDim.x + threadIdx.x) >> 5;
    int lane = threadIdx.x & 31;
    if (r >= NND) return;
    int beg = g_rowptr[r];
    int cnt = g_deg[r] - 1;
    float dr = g_dinv[r];
    const __half* xw = g_bufXW;
    float4 acc = h8_to_f4(*(const uint2*)(xw + (size_t)r * HD + lane * 4));
    int j = 0;
    for (; j + 8 <= cnt; j += 8) {
        uint2 u[8];
#pragma unroll
        for (int q = 0; q < 8; q++) {
            int c = g_csrcol[beg + j + q];
            u[q] = *(const uint2*)(xw + (size_t)c * HD + lane * 4);
        }
#pragma unroll
        for (int q = 0; q < 8; q++) {
            float4 v = h8_to_f4(u[q]);
            acc.x += v.x; acc.y += v.y; acc.z += v.z; acc.w += v.w;
        }
    }
    for (; j < cnt; j++) {
        int c = g_csrcol[beg + j];
        float4 v = h8_to_f4(*(const uint2*)(xw + (size_t)c * HD + lane * 4));
        acc.x += v.x; acc.y += v.y; acc.z += v.z; acc.w += v.w;
    }
    float4 b = *(const float4*)(bias + lane * 4);
    acc.x = fmaxf(acc.x * dr + b.x, 0.f);
    acc.y = fmaxf(acc.y * dr + b.y, 0.f);
    acc.z = fmaxf(acc.z * dr + b.z, 0.f);
    acc.w = fmaxf(acc.w * dr + b.w, 0.f);
    *(float4*)(g_bufACC + (size_t)r * HD + lane * 4) = acc;
}

// ---------------- fused GAT: blocked single-pass online softmax (fp16 gathered) -----
__device__ __forceinline__ float warp_sum(float s) {
#pragma unroll
    for (int o = 16; o; o >>= 1) s += __shfl_xor_sync(0xffffffffu, s, o);
    return s;
}
__global__ __launch_bounds__(256) void k_gat() {
    int r = (blockIdx.x * blockDim.x + threadIdx.x) >> 5;
    int lane = threadIdx.x & 31;
    if (r >= NND) return;
    int beg = g_rowptr[r];
    int cnt = g_deg[r] - 1;
    const __half* hh = g_bufHH;
    float4 hr = h8_to_f4(*(const uint2*)(hh + (size_t)r * HD + lane * 4));
    float m = warp_sum(hr.x * hr.x + hr.y * hr.y + hr.z * hr.z + hr.w * hr.w);
    float denom = 1.f;
    float4 acc = hr;
    int j = 0;
    for (; j + 4 <= cnt; j += 4) {
        int c0 = g_csrcol[beg + j];
        int c1 = g_csrcol[beg + j + 1];
        int c2 = g_csrcol[beg + j + 2];
        int c3 = g_csrcol[beg + j + 3];
        float4 h0 = h8_to_f4(*(const uint2*)(hh + (size_t)c0 * HD + lane * 4));
        float4 h1 = h8_to_f4(*(const uint2*)(hh + (size_t)c1 * HD + lane * 4));
        float4 h2 = h8_to_f4(*(const uint2*)(hh + (size_t)c2 * HD + lane * 4));
        float4 h3 = h8_to_f4(*(const uint2*)(hh + (size_t)c3 * HD + lane * 4));
        float d0 = hr.x * h0.x + hr.y * h0.y + hr.z * h0.z + hr.w * h0.w;
        float d1 = hr.x * h1.x + hr.y * h1.y + hr.z * h1.z + hr.w * h1.w;
        float d2 = hr.x * h2.x + hr.y * h2.y + hr.z * h2.z + hr.w * h2.w;
        float d3 = hr.x * h3.x + hr.y * h3.y + hr.z * h3.z + hr.w * h3.w;
#pragma unroll
        for (int o = 16; o; o >>= 1) {
            d0 += __shfl_xor_sync(0xffffffffu, d0, o);
            d1 += __shfl_xor_sync(0xffffffffu, d1, o);
            d2 += __shfl_xor_sync(0xffffffffu, d2, o);
            d3 += __shfl_xor_sync(0xffffffffu, d3, o);
        }
        float a0 = (c0 == r) ? -CUDART_INF_F : ((d0 > 0.f) ? d0 : 0.2f * d0);
        float a1 = (c1 == r) ? -CUDART_INF_F : ((d1 > 0.f) ? d1 : 0.2f * d1);
        float a2 = (c2 == r) ? -CUDART_INF_F : ((d2 > 0.f) ? d2 : 0.2f * d2);
        float a3 = (c3 == r) ? -CUDART_INF_F : ((d3 > 0.f) ? d3 : 0.2f * d3);
        float mblk = fmaxf(fmaxf(a0, a1), fmaxf(a2, a3));
        float mn = fmaxf(m, mblk);
        float sOld = __expf(m - mn);
        float e0 = __expf(a0 - mn);
        float e1 = __expf(a1 - mn);
        float e2 = __expf(a2 - mn);
        float e3 = __expf(a3 - mn);
        denom = denom * sOld + ((e0 + e1) + (e2 + e3));
        acc.x = acc.x * sOld + e0 * h0.x + e1 * h1.x + e2 * h2.x + e3 * h3.x;
        acc.y = acc.y * sOld + e0 * h0.y + e1 * h1.y + e2 * h2.y + e3 * h3.y;
        acc.z = acc.z * sOld + e0 * h0.z + e1 * h1.z + e2 * h2.z + e3 * h3.z;
        acc.w = acc.w * sOld + e0 * h0.w + e1 * h1.w + e2 * h2.w + e3 * h3.w;
        m = mn;
    }
    for (; j < cnt; j++) {
        int c = g_csrcol[beg + j];
        if (c == r) continue;
        float4 hc = h8_to_f4(*(const uint2*)(hh + (size_t)c * HD + lane * 4));
        float d = warp_sum(hr.x * hc.x + hr.y * hc.y + hr.z * hc.z + hr.w * hc.w);
        float al = (d > 0.f) ? d : 0.2f * d;
        float mn = fmaxf(m, al);
        float sOld = __expf(m - mn);
        float eNew = __expf(al - mn);
        denom = denom * sOld + eNew;
        acc.x = acc.x * sOld + eNew * hc.x;
        acc.y = acc.y * sOld + eNew * hc.y;
        acc.z = acc.z * sOld + eNew * hc.z;
        acc.w = acc.w * sOld + eNew * hc.w;
        m = mn;
    }
    float inv = 1.f / fmaxf(denom, 1e-16f);
    acc.x *= inv; acc.y *= inv; acc.z *= inv; acc.w *= inv;
    *(float4*)(g_bufOUT + (size_t)r * HD + lane * 4) = acc;
}

// ---------------- final mean pool ----------------
__global__ void k_zero_out(float* out) {
    int t = threadIdx.x;
    if (t < 2 * HD) out[t] = 0.f;
}
__global__ void k_mean(float* __restrict__ out) {
    int col = threadIdx.x;                    // 128 threads
    float s = 0.f;
    for (int i = blockIdx.x; i < NND; i += gridDim.x)
        s += g_bufOUT[(size_t)i * HD + col];
    s *= (1.0f / NND);
    atomicAdd(&out[col], s);
    atomicAdd(&out[col + HD], s);
}

// ---------------- launch ----------------
extern "C" void kernel_launch(void* const* d_in, const int* in_sizes, int n_in,
                              void* d_out, int out_size) {
    const float* x   = (const float*)d_in[0];
    const int*   ei  = (const int*)d_in[1];     // int32 (JAX x64 disabled)
    int E = in_sizes[1] / 2;
    const int* row = ei;
    const int* col = ei + E;
    const float* Wg[3] = {(const float*)d_in[2], (const float*)d_in[6],  (const float*)d_in[10]};
    const float* bg[3] = {(const float*)d_in[3], (const float*)d_in[7],  (const float*)d_in[11]};
    const float* Wa[3] = {(const float*)d_in[4], (const float*)d_in[8],  (const float*)d_in[12]};
    const float* ba[3] = {(const float*)d_in[5], (const float*)d_in[9],  (const float*)d_in[13]};
    float* out = (float*)d_out;

    __half *pXW, *pHH;
    float *pACC, *pOUT, *pDinv;
    cudaGetSymbolAddress((void**)&pXW,  g_bufXW);
    cudaGetSymbolAddress((void**)&pHH,  g_bufHH);
    cudaGetSymbolAddress((void**)&pACC, g_bufACC);
    cudaGetSymbolAddress((void**)&pOUT, g_bufOUT);
    cudaGetSymbolAddress((void**)&pDinv, g_dinv);

    const int TB = 256;
    int gN  = (NND + TB - 1) / TB;              // 157
    int gE  = (E + TB - 1) / TB;
    int gNw = (NND + 7) / 8;
    int gGemm = (NND + 127) / 128;              // 313

    k_deg_init<<<gN, TB>>>();
    k_deg_count<<<gE, TB>>>(row, E);
    k_scanA<<<gN, TB>>>();                      // also computes dinv
    k_scanB<<<1, TB>>>(gN);
    k_scanC<<<gN, TB>>>();
    k_fill<<<gE, TB>>>(row, col, E);

    const float* cur = x;
    for (int l = 0; l < 3; l++) {
        k_bperm<<<64, TB>>>(Wg[l], l > 0 ? 1 : 0);
        k_gemm_tf32<<<gGemm, TB>>>(cur, nullptr, pDinv, pXW, NND);   // xwS = xw * dinv
        k_gcn<<<gNw, TB>>>(bg[l]);
        k_bperm<<<64, TB>>>(Wa[l], 0);
        k_gemm_tf32<<<gGemm, TB>>>(pACC, ba[l], nullptr, pHH, NND);
        k_gat<<<gNw, TB>>>();
        cur = pOUT;
    }
    k_zero_out<<<1, TB>>>(out);
    k_mean<<<512, HD>>>(out);
}